// round 12
// baseline (speedup 1.0000x reference)
#include <cuda_runtime.h>
#include <cuda_bf16.h>
#include <cstdint>

// ISTA deconvolution via mma.sync bf16 tensor cores (round 12).
// tcgen05 is NOT available (harness PTX targets compute_103 without 'a');
// baseline ldmatrix + mma.sync.m16n8k16 bf16 IS.
//
// GEMM orientation (Toeplitz as A, signal as B):
//   D[m, n] = sum_kk A[mi][kk] * B[16w + kk][n]
//   A[mi][kk] = w[kk - mi - 1]            (16 x 144 band Toeplitz, shared)
//   B[jj][n]  = signal[r0 + n][c0 - 64 + jj]   (jj in [0,256))
// => D[mi, n] = sum_d w[d] * signal[r0+n][ (c0+16w+mi) + d - 63 ]  (TF SAME)
// Stage 1: w = delta63 - h  -> D = residual, stored TRANSPOSED g_resid[col][row]
// Stage 2: w = h reversed   -> D = update u; ISTA closed form:
//   x_T = T * sign(s*u) * max(|s*u| - lambda, 0)
// Precision: split bf16 (hi + lo), 3 MMA combos, fp32 accumulate.

#define LDIM 4096
#define BDIM 4096
#define KW   128
#define LAMBDA 0.1f
#define TITER  5.0f
#define NTH  256

#define AS   152                     // A smem stride (bf16), 304B = 19*16 -> conflict-free
#define BS0  264                     // mode0 B stride [n][jj], 528B = 33*16
#define BS1  72                      // mode1 B stride [jj][n], 144B = 9*16
#define A_BYTES (16 * AS * 2)        // 4864
#define B_BYTES (256 * BS1 * 2)      // 36864 (>= 64*BS0*2 = 33792)
#define SM_AHI 0
#define SM_ALO (A_BYTES)
#define SM_BHI (2 * A_BYTES)
#define SM_BLO (2 * A_BYTES + B_BYTES)
#define SM_TOTAL (2 * A_BYTES + 2 * B_BYTES)   // 83456 B -> 2 CTAs/SM

__device__ float g_resid[(size_t)BDIM * LDIM];   // residual, TRANSPOSED [col][row]

__device__ __forceinline__ uint32_t smem_u32(const void* p) {
    uint32_t a;
    asm("{ .reg .u64 t; cvta.to.shared.u64 t, %1; cvt.u32.u64 %0, t; }"
        : "=r"(a) : "l"(p));
    return a;
}
__device__ __forceinline__ void ldsm_x4(uint32_t* r, uint32_t addr) {
    asm volatile("ldmatrix.sync.aligned.m8n8.x4.shared.b16 {%0,%1,%2,%3}, [%4];"
        : "=r"(r[0]), "=r"(r[1]), "=r"(r[2]), "=r"(r[3]) : "r"(addr));
}
__device__ __forceinline__ void ldsm_x4_t(uint32_t* r, uint32_t addr) {
    asm volatile("ldmatrix.sync.aligned.m8n8.x4.trans.shared.b16 {%0,%1,%2,%3}, [%4];"
        : "=r"(r[0]), "=r"(r[1]), "=r"(r[2]), "=r"(r[3]) : "r"(addr));
}
__device__ __forceinline__ void mma_bf16(float* c, const uint32_t* a, const uint32_t* b) {
    asm volatile(
        "mma.sync.aligned.m16n8k16.row.col.f32.bf16.bf16.f32 "
        "{%0,%1,%2,%3}, {%4,%5,%6,%7}, {%8,%9}, {%0,%1,%2,%3};"
        : "+f"(c[0]), "+f"(c[1]), "+f"(c[2]), "+f"(c[3])
        : "r"(a[0]), "r"(a[1]), "r"(a[2]), "r"(a[3]), "r"(b[0]), "r"(b[1]));
}
__device__ __forceinline__ void split_bf16(float v, __nv_bfloat16& hi, __nv_bfloat16& lo) {
    hi = __float2bfloat16(v);
    lo = __float2bfloat16(v - __bfloat162float(hi));
}

__global__ __launch_bounds__(NTH, 2)
void conv_mma_kernel(const float* __restrict__ y,
                     const float* __restrict__ h,
                     const float* __restrict__ step,
                     float* __restrict__ out,
                     int mode)   // 0: y -> residual (transposed scratch); 1: resid -> ISTA out
{
    extern __shared__ __align__(16) char smem[];
    const int tid = threadIdx.x, w = tid >> 5, lane = tid & 31;
    const int c0 = blockIdx.x * 128;   // output column tile
    const int r0 = blockIdx.y * 64;    // batch row tile
    __nv_bfloat16* Ahi = (__nv_bfloat16*)(smem + SM_AHI);
    __nv_bfloat16* Alo = (__nv_bfloat16*)(smem + SM_ALO);
    __nv_bfloat16* Bhi = (__nv_bfloat16*)(smem + SM_BHI);
    __nv_bfloat16* Blo = (__nv_bfloat16*)(smem + SM_BLO);

    // ---- Build Toeplitz A (16 x 144), split hi/lo ----
    for (int idx = tid; idx < 16 * 144; idx += NTH) {
        int mi = idx / 144, jj = idx - mi * 144;
        int d = jj - mi - 1;
        float wv = 0.0f;
        if (0 <= d && d < KW)
            wv = (mode == 0) ? ((d == 63) ? 1.0f : 0.0f) - __ldg(h + d)
                             : __ldg(h + (KW - 1) - d);
        __nv_bfloat16 hi, lo;
        split_bf16(wv, hi, lo);
        Ahi[mi * AS + jj] = hi;
        Alo[mi * AS + jj] = lo;
    }

    // ---- Stage B tile, split hi/lo ----
    if (mode == 0) {
        // B[n][jj] = y[r0+n][c0-64+jj], layout [64][BS0]
        for (int idx = tid; idx < 64 * 64; idx += NTH) {
            int n = idx >> 6, q = idx & 63;
            int gc = c0 - 64 + 4 * q;                 // multiple of 4
            const float* base = y + (size_t)(r0 + n) * LDIM;
            float4 f;
            if ((unsigned)gc <= (unsigned)(LDIM - 4)) {
                f = *(const float4*)(base + gc);
            } else {
                f.x = ((unsigned)(gc + 0) < LDIM) ? base[gc + 0] : 0.0f;
                f.y = ((unsigned)(gc + 1) < LDIM) ? base[gc + 1] : 0.0f;
                f.z = ((unsigned)(gc + 2) < LDIM) ? base[gc + 2] : 0.0f;
                f.w = ((unsigned)(gc + 3) < LDIM) ? base[gc + 3] : 0.0f;
            }
            __nv_bfloat16 h0, l0, h1, l1, h2, l2, h3, l3;
            split_bf16(f.x, h0, l0); split_bf16(f.y, h1, l1);
            split_bf16(f.z, h2, l2); split_bf16(f.w, h3, l3);
            __nv_bfloat162* dh = (__nv_bfloat162*)(Bhi + n * BS0 + 4 * q);
            __nv_bfloat162* dl = (__nv_bfloat162*)(Blo + n * BS0 + 4 * q);
            dh[0] = __halves2bfloat162(h0, h1); dh[1] = __halves2bfloat162(h2, h3);
            dl[0] = __halves2bfloat162(l0, l1); dl[1] = __halves2bfloat162(l2, l3);
        }
    } else {
        // B[jj][n] = g_resid[c0-64+jj][r0+n], layout [256][BS1]
        for (int idx = tid; idx < 256 * 16; idx += NTH) {
            int jj = idx >> 4, q = idx & 15;
            int gc = c0 - 64 + jj;
            float4 f = make_float4(0.f, 0.f, 0.f, 0.f);
            if ((unsigned)gc < (unsigned)LDIM)
                f = *(const float4*)(g_resid + (size_t)gc * LDIM + r0 + 4 * q);
            __nv_bfloat16 h0, l0, h1, l1, h2, l2, h3, l3;
            split_bf16(f.x, h0, l0); split_bf16(f.y, h1, l1);
            split_bf16(f.z, h2, l2); split_bf16(f.w, h3, l3);
            __nv_bfloat162* dh = (__nv_bfloat162*)(Bhi + jj * BS1 + 4 * q);
            __nv_bfloat162* dl = (__nv_bfloat162*)(Blo + jj * BS1 + 4 * q);
            dh[0] = __halves2bfloat162(h0, h1); dh[1] = __halves2bfloat162(h2, h3);
            dl[0] = __halves2bfloat162(l0, l1); dl[1] = __halves2bfloat162(l2, l3);
        }
    }
    __syncthreads();

    // ---- MMA mainloop: 9 ksteps x 4 ntile-pairs x (hi*hi + hi*lo + lo*hi) ----
    float acc[8][4];
#pragma unroll
    for (int i = 0; i < 8; i++)
#pragma unroll
        for (int j = 0; j < 4; j++) acc[i][j] = 0.0f;

    const uint32_t sb = smem_u32(smem);
    // A ldmatrix lane address: row = lane&15, col half = +8 for lanes 16-31.
    const uint32_t aBase = sb + SM_AHI + (((lane & 15) * AS + ((lane & 16) ? 8 : 0)) << 1);
    // B mode0 (non-trans, [n][jj]): mats (n0-7,j0-7),(n0-7,j8-15),(n8-15,j0-7),(n8-15,j8-15)
    const uint32_t b0n = (lane & 7) + ((lane & 16) ? 8 : 0);
    const uint32_t b0j = (lane & 8) ? 8 : 0;
    // B mode1 (trans, [jj][n]): mats (k0-7,n0-7),(k8-15,n0-7),(k0-7,n8-15),(k8-15,n8-15)
    const uint32_t b1j = (lane & 15);
    const uint32_t b1n = (lane & 16) ? 8 : 0;

#pragma unroll
    for (int s = 0; s < 9; s++) {
        uint32_t ah[4], al[4];
        ldsm_x4(ah, aBase + (uint32_t)(32 * s));            // 16s bf16 = 32B
        ldsm_x4(al, aBase + (uint32_t)(A_BYTES + 32 * s));
        const int jj0 = 16 * (w + s);
#pragma unroll
        for (int p = 0; p < 4; p++) {
            uint32_t bh[4], bl[4];
            if (mode == 0) {
                uint32_t ad = sb + SM_BHI +
                    ((((16 * p + b0n) * BS0) + (uint32_t)jj0 + b0j) << 1);
                ldsm_x4(bh, ad);
                ldsm_x4(bl, ad + B_BYTES);
            } else {
                uint32_t ad = sb + SM_BHI +
                    (((((uint32_t)jj0 + b1j) * BS1) + 16 * p + b1n) << 1);
                ldsm_x4_t(bh, ad);
                ldsm_x4_t(bl, ad + B_BYTES);
            }
            mma_bf16(acc[2 * p],     ah, bh);        // hi*hi, ntile 2p
            mma_bf16(acc[2 * p],     ah, bl);        // hi*lo
            mma_bf16(acc[2 * p],     al, bh);        // lo*hi
            mma_bf16(acc[2 * p + 1], ah, bh + 2);    // ntile 2p+1
            mma_bf16(acc[2 * p + 1], ah, bl + 2);
            mma_bf16(acc[2 * p + 1], al, bh + 2);
        }
    }

    // ---- Epilogue ----
    // C frag: c0=(mi=lane>>2, n=2*(lane&3)), c1=n+1, c2=(mi+8,n), c3=(mi+8,n+1).
    const int mi = lane >> 2;
    const int nf = (lane & 3) * 2;
    const int mg = c0 + 16 * w + mi;     // output column
    if (mode == 0) {
        // residual, transposed: g_resid[col][row]
#pragma unroll
        for (int nt = 0; nt < 8; nt++) {
            int rg = r0 + 8 * nt + nf;
            *(float2*)(g_resid + (size_t)mg * LDIM + rg) =
                make_float2(acc[nt][0], acc[nt][1]);
            *(float2*)(g_resid + (size_t)(mg + 8) * LDIM + rg) =
                make_float2(acc[nt][2], acc[nt][3]);
        }
    } else {
        const float sv = __ldg(step);
#pragma unroll
        for (int nt = 0; nt < 8; nt++) {
            int rg = r0 + 8 * nt + nf;
            float a0 = sv * acc[nt][0];
            float a1 = sv * acc[nt][1];
            float a2 = sv * acc[nt][2];
            float a3 = sv * acc[nt][3];
            out[(size_t)rg * LDIM + mg] =
                copysignf(TITER * fmaxf(fabsf(a0) - LAMBDA, 0.0f), a0);
            out[(size_t)(rg + 1) * LDIM + mg] =
                copysignf(TITER * fmaxf(fabsf(a1) - LAMBDA, 0.0f), a1);
            out[(size_t)rg * LDIM + mg + 8] =
                copysignf(TITER * fmaxf(fabsf(a2) - LAMBDA, 0.0f), a2);
            out[(size_t)(rg + 1) * LDIM + mg + 8] =
                copysignf(TITER * fmaxf(fabsf(a3) - LAMBDA, 0.0f), a3);
        }
    }
}

extern "C" void kernel_launch(void* const* d_in, const int* in_sizes, int n_in,
                              void* d_out, int out_size)
{
    const float* y = nullptr;
    const float* h = nullptr;
    const float* s = nullptr;
    for (int i = 0; i < n_in; i++) {
        if (in_sizes[i] == BDIM * LDIM)      y = (const float*)d_in[i];
        else if (in_sizes[i] == KW)          h = (const float*)d_in[i];
        else if (in_sizes[i] == 1)           s = (const float*)d_in[i];
    }
    cudaFuncSetAttribute(conv_mma_kernel,
                         cudaFuncAttributeMaxDynamicSharedMemorySize, SM_TOTAL);
    dim3 grid(LDIM / 128, BDIM / 64);
    conv_mma_kernel<<<grid, NTH, SM_TOTAL>>>(y, h, s, (float*)d_out, 0);
    conv_mma_kernel<<<grid, NTH, SM_TOTAL>>>(y, h, s, (float*)d_out, 1);
}

// round 13
// speedup vs baseline: 1.3755x; 1.3755x over previous
#include <cuda_runtime.h>
#include <cuda_bf16.h>
#include <cstdint>

// ISTA deconvolution via mma.sync bf16 (round 13).
// R12 math/fragment-mappings (verified: rel_err 5.6e-6), rescheduled:
//  - combo-major MMA order: RAW distance 4 MMAs instead of 0.
//  - 32 batch rows per CTA, launch_bounds(256,3) -> 3 CTAs/SM, 24 warps.
//  - templated mode (0: y->resid transposed scratch; 1: resid->ISTA out),
//    mode1 output routed through SMEM transpose -> coalesced float4 stores.
// D[m,n] = sum A[mi][kk]*B[16w+kk][n], A = 16x144 band Toeplitz (w[kk-mi-1]),
// stage0 w = delta63 - h (emits residual), stage1 w = h reversed.
// Split bf16 (hi+lo), combos hh+hl+lh, fp32 accumulate.

#define LDIM 4096
#define BDIM 4096
#define KW   128
#define LAMBDA 0.1f
#define TITER  5.0f
#define NTH  256
#define ROWS 32                      // batch rows per CTA
#define COLS 128                     // output columns per CTA (8 warps x 16)

#define AS   152                     // A stride (bf16): 304B = 19*16 -> conflict-free
#define A_BYTES (16 * AS * 2)        // 4864
#define BS0  264                     // mode0 B stride [n][jj] (528B = 33*16)
#define BS1  40                      // mode1 B stride [jj][n] (80B = 5*16)
#define B0_BYTES (ROWS * BS0 * 2)    // 16896
#define B1_BYTES (256 * BS1 * 2)     // 20480
#define SM_AHI 0
#define SM_ALO A_BYTES
#define SM_BHI (2 * A_BYTES)         // 9728
#define SMT0 (SM_BHI + 2 * B0_BYTES) // 43520
#define SMT1 (SM_BHI + 2 * B1_BYTES) // 50688

__device__ float g_resid[(size_t)BDIM * LDIM];   // residual, TRANSPOSED [col][row]

__device__ __forceinline__ uint32_t smem_u32(const void* p) {
    uint32_t a;
    asm("{ .reg .u64 t; cvta.to.shared.u64 t, %1; cvt.u32.u64 %0, t; }"
        : "=r"(a) : "l"(p));
    return a;
}
__device__ __forceinline__ void ldsm_x4(uint32_t* r, uint32_t addr) {
    asm volatile("ldmatrix.sync.aligned.m8n8.x4.shared.b16 {%0,%1,%2,%3}, [%4];"
        : "=r"(r[0]), "=r"(r[1]), "=r"(r[2]), "=r"(r[3]) : "r"(addr));
}
__device__ __forceinline__ void ldsm_x4_t(uint32_t* r, uint32_t addr) {
    asm volatile("ldmatrix.sync.aligned.m8n8.x4.trans.shared.b16 {%0,%1,%2,%3}, [%4];"
        : "=r"(r[0]), "=r"(r[1]), "=r"(r[2]), "=r"(r[3]) : "r"(addr));
}
__device__ __forceinline__ void mma_bf16(float* c, const uint32_t* a, const uint32_t* b) {
    asm volatile(
        "mma.sync.aligned.m16n8k16.row.col.f32.bf16.bf16.f32 "
        "{%0,%1,%2,%3}, {%4,%5,%6,%7}, {%8,%9}, {%0,%1,%2,%3};"
        : "+f"(c[0]), "+f"(c[1]), "+f"(c[2]), "+f"(c[3])
        : "r"(a[0]), "r"(a[1]), "r"(a[2]), "r"(a[3]), "r"(b[0]), "r"(b[1]));
}
__device__ __forceinline__ void split_bf16(float v, __nv_bfloat16& hi, __nv_bfloat16& lo) {
    hi = __float2bfloat16(v);
    lo = __float2bfloat16(v - __bfloat162float(hi));
}

template <int MODE>
__global__ __launch_bounds__(NTH, 3)
void conv_mma_kernel(const float* __restrict__ y,
                     const float* __restrict__ h,
                     const float* __restrict__ step,
                     float* __restrict__ out)
{
    extern __shared__ __align__(16) char smem[];
    constexpr int B_BYTES = (MODE == 0) ? B0_BYTES : B1_BYTES;
    const int tid = threadIdx.x, w = tid >> 5, lane = tid & 31;
    const int c0 = blockIdx.x * COLS;
    const int r0 = blockIdx.y * ROWS;
    __nv_bfloat16* Ahi = (__nv_bfloat16*)(smem + SM_AHI);
    __nv_bfloat16* Alo = (__nv_bfloat16*)(smem + SM_ALO);
    __nv_bfloat16* Bhi = (__nv_bfloat16*)(smem + SM_BHI);
    __nv_bfloat16* Blo = (__nv_bfloat16*)(smem + SM_BHI + B_BYTES);

    // ---- Toeplitz A (16 x 144), split hi/lo ----
    for (int idx = tid; idx < 16 * 144; idx += NTH) {
        int mi = idx / 144, jj = idx - mi * 144;
        int d = jj - mi - 1;
        float wv = 0.0f;
        if (0 <= d && d < KW)
            wv = (MODE == 0) ? ((d == 63) ? 1.0f : 0.0f) - __ldg(h + d)
                             : __ldg(h + (KW - 1) - d);
        __nv_bfloat16 hi, lo;
        split_bf16(wv, hi, lo);
        Ahi[mi * AS + jj] = hi;
        Alo[mi * AS + jj] = lo;
    }

    // ---- Stage B tile, split hi/lo ----
    if (MODE == 0) {
        // B[n][jj] = y[r0+n][c0-64+jj]
#pragma unroll
        for (int it = 0; it < 8; it++) {
            int idx = tid + it * NTH;            // 32*64 items
            int n = idx >> 6, q = idx & 63;
            int gc = c0 - 64 + 4 * q;
            const float* base = y + (size_t)(r0 + n) * LDIM;
            float4 f;
            if ((unsigned)gc <= (unsigned)(LDIM - 4)) {
                f = *(const float4*)(base + gc);
            } else {
                f.x = ((unsigned)(gc + 0) < LDIM) ? base[gc + 0] : 0.0f;
                f.y = ((unsigned)(gc + 1) < LDIM) ? base[gc + 1] : 0.0f;
                f.z = ((unsigned)(gc + 2) < LDIM) ? base[gc + 2] : 0.0f;
                f.w = ((unsigned)(gc + 3) < LDIM) ? base[gc + 3] : 0.0f;
            }
            __nv_bfloat16 h0, l0, h1, l1, h2, l2, h3, l3;
            split_bf16(f.x, h0, l0); split_bf16(f.y, h1, l1);
            split_bf16(f.z, h2, l2); split_bf16(f.w, h3, l3);
            __nv_bfloat162* dh = (__nv_bfloat162*)(Bhi + n * BS0 + 4 * q);
            __nv_bfloat162* dl = (__nv_bfloat162*)(Blo + n * BS0 + 4 * q);
            dh[0] = __halves2bfloat162(h0, h1); dh[1] = __halves2bfloat162(h2, h3);
            dl[0] = __halves2bfloat162(l0, l1); dl[1] = __halves2bfloat162(l2, l3);
        }
    } else {
        // B[jj][n] = g_resid[c0-64+jj][r0+n]
#pragma unroll
        for (int it = 0; it < 8; it++) {
            int idx = tid + it * NTH;            // 256*8 items
            int jj = idx >> 3, q = idx & 7;
            int gc = c0 - 64 + jj;
            float4 f = make_float4(0.f, 0.f, 0.f, 0.f);
            if ((unsigned)gc < (unsigned)LDIM)
                f = *(const float4*)(g_resid + (size_t)gc * LDIM + r0 + 4 * q);
            __nv_bfloat16 h0, l0, h1, l1, h2, l2, h3, l3;
            split_bf16(f.x, h0, l0); split_bf16(f.y, h1, l1);
            split_bf16(f.z, h2, l2); split_bf16(f.w, h3, l3);
            __nv_bfloat162* dh = (__nv_bfloat162*)(Bhi + jj * BS1 + 4 * q);
            __nv_bfloat162* dl = (__nv_bfloat162*)(Blo + jj * BS1 + 4 * q);
            dh[0] = __halves2bfloat162(h0, h1); dh[1] = __halves2bfloat162(h2, h3);
            dl[0] = __halves2bfloat162(l0, l1); dl[1] = __halves2bfloat162(l2, l3);
        }
    }
    __syncthreads();

    // ---- MMA mainloop: 9 ksteps; per s: 6 LDSM then 12 MMAs combo-major ----
    float acc[4][4];
#pragma unroll
    for (int i = 0; i < 4; i++)
#pragma unroll
        for (int j = 0; j < 4; j++) acc[i][j] = 0.0f;

    const uint32_t sb = smem_u32(smem);
    const uint32_t aHi = sb + SM_AHI + (((lane & 15) * AS + ((lane & 16) ? 8 : 0)) << 1);
    uint32_t bA0, bA1;
    if (MODE == 0) {
        uint32_t b0n = (lane & 7) + ((lane & 16) ? 8 : 0);
        uint32_t b0j = (lane & 8) ? 8 : 0;
        bA0 = sb + SM_BHI + (((0 + b0n) * BS0 + b0j) << 1);
        bA1 = sb + SM_BHI + (((16 + b0n) * BS0 + b0j) << 1);
    } else {
        uint32_t b1j = lane & 15, b1n = (lane & 16) ? 8 : 0;
        bA0 = sb + SM_BHI + ((b1j * BS1 + 0 + b1n) << 1);
        bA1 = sb + SM_BHI + ((b1j * BS1 + 16 + b1n) << 1);
    }

#pragma unroll
    for (int s = 0; s < 9; s++) {
        uint32_t ah[4], al[4], bh0[4], bh1[4], bl0[4], bl1[4];
        ldsm_x4(ah, aHi + 32u * s);
        ldsm_x4(al, aHi + (uint32_t)A_BYTES + 32u * s);
        const uint32_t jj0 = 16u * (w + s);
        const uint32_t bo = (MODE == 0) ? (jj0 << 1) : (jj0 * BS1 * 2u);
        if (MODE == 0) {
            ldsm_x4(bh0, bA0 + bo); ldsm_x4(bh1, bA1 + bo);
            ldsm_x4(bl0, bA0 + bo + B_BYTES); ldsm_x4(bl1, bA1 + bo + B_BYTES);
        } else {
            ldsm_x4_t(bh0, bA0 + bo); ldsm_x4_t(bh1, bA1 + bo);
            ldsm_x4_t(bl0, bA0 + bo + B_BYTES); ldsm_x4_t(bl1, bA1 + bo + B_BYTES);
        }
        // combo-major: 4 independent accumulator chains per combo
        mma_bf16(acc[0], ah, bh0); mma_bf16(acc[1], ah, bh0 + 2);
        mma_bf16(acc[2], ah, bh1); mma_bf16(acc[3], ah, bh1 + 2);
        mma_bf16(acc[0], ah, bl0); mma_bf16(acc[1], ah, bl0 + 2);
        mma_bf16(acc[2], ah, bl1); mma_bf16(acc[3], ah, bl1 + 2);
        mma_bf16(acc[0], al, bh0); mma_bf16(acc[1], al, bh0 + 2);
        mma_bf16(acc[2], al, bh1); mma_bf16(acc[3], al, bh1 + 2);
    }

    // ---- Epilogue ----
    const int mi = lane >> 2;
    const int nf = (lane & 3) * 2;
    const int mg = c0 + 16 * w + mi;      // output column
    if (MODE == 0) {
#pragma unroll
        for (int t = 0; t < 4; t++) {
            int rg = r0 + 8 * t + nf;
            *(float2*)(g_resid + (size_t)mg * LDIM + rg) =
                make_float2(acc[t][0], acc[t][1]);
            *(float2*)(g_resid + (size_t)(mg + 8) * LDIM + rg) =
                make_float2(acc[t][2], acc[t][3]);
        }
    } else {
        // transpose via SMEM (B region is free after all warps pass this sync)
        __syncthreads();
        float* smT = (float*)(smem + SM_BHI);   // [32][132]
        const int cw = 16 * w + mi;
#pragma unroll
        for (int t = 0; t < 4; t++) {
            smT[(8 * t + nf) * 132 + cw]         = acc[t][0];
            smT[(8 * t + nf + 1) * 132 + cw]     = acc[t][1];
            smT[(8 * t + nf) * 132 + cw + 8]     = acc[t][2];
            smT[(8 * t + nf + 1) * 132 + cw + 8] = acc[t][3];
        }
        __syncthreads();
        const float sv = __ldg(step);
        const int n = tid >> 3, cq = tid & 7;
        const float* srow = smT + n * 132 + 16 * cq;
        float4* orow = (float4*)(out + (size_t)(r0 + n) * LDIM + c0 + 16 * cq);
#pragma unroll
        for (int i = 0; i < 4; i++) {
            float a0 = sv * srow[4 * i + 0];
            float a1 = sv * srow[4 * i + 1];
            float a2 = sv * srow[4 * i + 2];
            float a3 = sv * srow[4 * i + 3];
            orow[i] = make_float4(
                copysignf(TITER * fmaxf(fabsf(a0) - LAMBDA, 0.0f), a0),
                copysignf(TITER * fmaxf(fabsf(a1) - LAMBDA, 0.0f), a1),
                copysignf(TITER * fmaxf(fabsf(a2) - LAMBDA, 0.0f), a2),
                copysignf(TITER * fmaxf(fabsf(a3) - LAMBDA, 0.0f), a3));
        }
    }
}

extern "C" void kernel_launch(void* const* d_in, const int* in_sizes, int n_in,
                              void* d_out, int out_size)
{
    const float* y = nullptr;
    const float* h = nullptr;
    const float* s = nullptr;
    for (int i = 0; i < n_in; i++) {
        if (in_sizes[i] == BDIM * LDIM)      y = (const float*)d_in[i];
        else if (in_sizes[i] == KW)          h = (const float*)d_in[i];
        else if (in_sizes[i] == 1)           s = (const float*)d_in[i];
    }
    cudaFuncSetAttribute(conv_mma_kernel<0>,
                         cudaFuncAttributeMaxDynamicSharedMemorySize, SMT0);
    cudaFuncSetAttribute(conv_mma_kernel<1>,
                         cudaFuncAttributeMaxDynamicSharedMemorySize, SMT1);
    dim3 grid(LDIM / COLS, BDIM / ROWS);   // (32, 128)
    conv_mma_kernel<0><<<grid, NTH, SMT0>>>(y, h, s, (float*)d_out);
    conv_mma_kernel<1><<<grid, NTH, SMT1>>>(y, h, s, (float*)d_out);
}